// round 1
// baseline (speedup 1.0000x reference)
#include <cuda_runtime.h>

// Problem constants
#define TT    4096
#define FF    9
#define NSEQ  2048      // 256*8
#define L1    2049      // pooled len after stage 1
#define L2    1025      // pooled len after stage 2
#define L3    513       // pooled len after stage 3

// Tiling
#define V3      62              // stage-3 pooled outputs per tile
#define NTILES  9               // ceil(513/62)
#define IN_LEN  (8*V3+14)       // 510 input samples needed per tile
#define IN_STR  516             // padded row stride (odd*4 banks -> low conflict)
#define S1_STR  264             // stage1 pooled buffer stride (len 254, reads <=257)
#define S2_STR  132             // stage2 pooled buffer stride (len 126, reads <=129)
#define W2_STR  49              // padded weight row strides (kill bank conflicts)
#define W3_STR  97

#define SM_FLOATS (9*IN_STR + 16*S1_STR + 32*S2_STR + 432 + 32*W2_STR + 16*W3_STR + 64 + 256)
#define SMEM_BYTES (SM_FLOATS * 4)

__device__ float g_feat[NSEQ * 16];

__global__ __launch_bounds__(256) void cnn_main(
    const float* __restrict__ x,
    const float* __restrict__ w1, const float* __restrict__ b1,
    const float* __restrict__ w2, const float* __restrict__ b2,
    const float* __restrict__ w3, const float* __restrict__ b3)
{
    extern __shared__ float sm[];
    float* h0  = sm;                      // [9][IN_STR]
    float* s1  = h0  + 9  * IN_STR;       // [16][S1_STR]
    float* s2  = s1  + 16 * S1_STR;       // [32][S2_STR]
    float* sw1 = s2  + 32 * S2_STR;       // [16][27]
    float* sw2 = sw1 + 432;               // [32][W2_STR]
    float* sw3 = sw2 + 32 * W2_STR;       // [16][W3_STR]
    float* sb  = sw3 + 16 * W3_STR;       // b1[0:16) b2[16:48) b3[48:64)
    float* facc= sb  + 64;                // [256] per-thread mean partials

    const int tid = threadIdx.x;
    const int n   = blockIdx.x;
    const float* xin = x + (size_t)n * (TT * FF);

    // Zero all smem once: provides zero padding everywhere, forever.
    for (int i = tid; i < SM_FLOATS; i += 256) sm[i] = 0.f;
    __syncthreads();

    // Load weights/biases (padded strides)
    for (int i = tid; i < 16*27; i += 256) sw1[i] = w1[i];
    for (int i = tid; i < 32*48; i += 256) sw2[(i/48)*W2_STR + (i%48)] = w2[i];
    for (int i = tid; i < 16*96; i += 256) sw3[(i/96)*W3_STR + (i%96)] = w3[i];
    if (tid < 16)      sb[tid] = b1[tid];
    else if (tid < 48) sb[tid] = b2[tid-16];
    else if (tid < 64) sb[tid] = b3[tid-48];
    __syncthreads();

    for (int tile = 0; tile < NTILES; ++tile) {
        const int va  = tile * V3;
        const int vb  = min(va + V3, L3);
        const int t0  = 8*va - 14;    // global t of h0 local index 0
        const int u1b = 4*va - 6;     // global stage1-pooled idx of s1 local 0
        const int u2b = 2*va - 2;     // global stage2-pooled idx of s2 local 0

        // ---- Phase A: coalesced load + transpose of input tile ----
        for (int idx = tid; idx < IN_LEN*FF; idx += 256) {
            int tl = idx / FF;
            int ci = idx - tl*FF;
            int t  = t0 + tl;
            float v = 0.f;
            if (t >= 0 && t < TT) v = xin[t*FF + ci];
            h0[ci*IN_STR + tl] = v;
        }
        __syncthreads();

        // ---- Phase B: stage1 conv(9->16,k3,p2) + relu + pool2 ----
        // item: cog in low 3 bits (broadcast-friendly), ug (u-quad) high
        #pragma unroll
        for (int it = 0; it < 2; ++it) {
            int item = tid + it*256;
            int cog = item & 7;
            int ug  = item >> 3;            // 0..63
            int co0 = cog * 2;
            int ul0 = ug * 4;
            float acc0[8], acc1[8];
            #pragma unroll
            for (int p = 0; p < 8; ++p) { acc0[p]=0.f; acc1[p]=0.f; }
            const float* wpa = sw1 + co0*27;
            const float* wpb = wpa + 27;
            const float* hp  = h0 + 2*ul0;
            #pragma unroll
            for (int ci = 0; ci < 9; ++ci) {
                float in[10];
                #pragma unroll
                for (int j = 0; j < 10; ++j) in[j] = hp[j];
                float wa0=wpa[0], wa1=wpa[1], wa2=wpa[2];
                float wb0=wpb[0], wb1=wpb[1], wb2=wpb[2];
                #pragma unroll
                for (int p = 0; p < 8; ++p) {
                    acc0[p] += wa0*in[p] + wa1*in[p+1] + wa2*in[p+2];
                    acc1[p] += wb0*in[p] + wb1*in[p+1] + wb2*in[p+2];
                }
                wpa += 3; wpb += 3; hp += IN_STR;
            }
            float ba = sb[co0], bb = sb[co0+1];
            #pragma unroll
            for (int u = 0; u < 4; ++u) {
                int ul  = ul0 + u;
                int ug1 = u1b + ul;
                bool valid = (ug1 >= 0) && (ug1 < L1);
                float v0 = fmaxf(fmaxf(acc0[2*u]+ba, 0.f), fmaxf(acc0[2*u+1]+ba, 0.f));
                float v1 = fmaxf(fmaxf(acc1[2*u]+bb, 0.f), fmaxf(acc1[2*u+1]+bb, 0.f));
                s1[ co0   *S1_STR + ul] = valid ? v0 : 0.f;
                s1[(co0+1)*S1_STR + ul] = valid ? v1 : 0.f;
            }
        }
        __syncthreads();

        // ---- Phase C: stage2 conv(16->32,k3,p2) + relu + pool2 ----
        #pragma unroll
        for (int it = 0; it < 2; ++it) {
            int item = tid + it*256;
            int cog = item & 15;
            int ug  = item >> 4;            // 0..31
            int co0 = cog * 2;
            int ul0 = ug * 4;
            float acc0[8], acc1[8];
            #pragma unroll
            for (int p = 0; p < 8; ++p) { acc0[p]=0.f; acc1[p]=0.f; }
            const float* wpa = sw2 + co0*W2_STR;
            const float* wpb = wpa + W2_STR;
            const float* hp  = s1 + 2*ul0;
            #pragma unroll 4
            for (int ci = 0; ci < 16; ++ci) {
                float in[10];
                #pragma unroll
                for (int j = 0; j < 10; ++j) in[j] = hp[j];
                float wa0=wpa[0], wa1=wpa[1], wa2=wpa[2];
                float wb0=wpb[0], wb1=wpb[1], wb2=wpb[2];
                #pragma unroll
                for (int p = 0; p < 8; ++p) {
                    acc0[p] += wa0*in[p] + wa1*in[p+1] + wa2*in[p+2];
                    acc1[p] += wb0*in[p] + wb1*in[p+1] + wb2*in[p+2];
                }
                wpa += 3; wpb += 3; hp += S1_STR;
            }
            float ba = sb[16+co0], bb = sb[16+co0+1];
            #pragma unroll
            for (int u = 0; u < 4; ++u) {
                int ul  = ul0 + u;
                int ug2 = u2b + ul;
                bool valid = (ug2 >= 0) && (ug2 < L2);
                float v0 = fmaxf(fmaxf(acc0[2*u]+ba, 0.f), fmaxf(acc0[2*u+1]+ba, 0.f));
                float v1 = fmaxf(fmaxf(acc1[2*u]+bb, 0.f), fmaxf(acc1[2*u+1]+bb, 0.f));
                s2[ co0   *S2_STR + ul] = valid ? v0 : 0.f;
                s2[(co0+1)*S2_STR + ul] = valid ? v1 : 0.f;
            }
        }
        __syncthreads();

        // ---- Phase D: stage3 conv(32->16,k3,p2) + relu + pool2 + mean-acc ----
        {
            int co  = tid & 15;
            int ug  = tid >> 4;             // 0..15
            int ul0 = ug * 4;
            float acc[8];
            #pragma unroll
            for (int p = 0; p < 8; ++p) acc[p] = 0.f;
            const float* wp = sw3 + co*W3_STR;
            const float* hp = s2 + 2*ul0;
            #pragma unroll 4
            for (int ci = 0; ci < 32; ++ci) {
                float in[10];
                #pragma unroll
                for (int j = 0; j < 10; ++j) in[j] = hp[j];
                float w0=wp[0], w1_=wp[1], w2_=wp[2];
                #pragma unroll
                for (int p = 0; p < 8; ++p)
                    acc[p] += w0*in[p] + w1_*in[p+1] + w2_*in[p+2];
                wp += 3; hp += S2_STR;
            }
            float b = sb[48+co];
            float sum = 0.f;
            #pragma unroll
            for (int u = 0; u < 4; ++u) {
                int v = va + ul0 + u;
                if (v < vb) {
                    float y = fmaxf(fmaxf(acc[2*u]+b, 0.f), fmaxf(acc[2*u+1]+b, 0.f));
                    sum += y;
                }
            }
            facc[tid] += sum;   // fixed slot per thread: deterministic
        }
        __syncthreads();
    }

    // ---- mean over L3=513 positions ----
    if (tid < 16) {
        float s = 0.f;
        #pragma unroll
        for (int u = 0; u < 16; ++u) s += facc[tid + 16*u];
        g_feat[n*16 + tid] = s * (1.0f / 513.0f);
    }
}

// Final: feat [B, J*16=128] -> maxpool k=3 -> [B, 42]
__global__ void final_pool(float* __restrict__ out)
{
    int i = blockIdx.x * blockDim.x + threadIdx.x;
    if (i >= 256*42) return;
    int b = i / 42;
    int g = i - b*42;
    float m = -1e30f;
    #pragma unroll
    for (int e3 = 0; e3 < 3; ++e3) {
        int e = 3*g + e3;
        int j = e >> 4;
        int c = e & 15;
        m = fmaxf(m, g_feat[(b*8 + j)*16 + c]);
    }
    out[i] = m;
}

extern "C" void kernel_launch(void* const* d_in, const int* in_sizes, int n_in,
                              void* d_out, int out_size)
{
    (void)in_sizes; (void)n_in; (void)out_size;
    const float* x  = (const float*)d_in[0];
    const float* w1 = (const float*)d_in[1];
    const float* b1 = (const float*)d_in[2];
    const float* w2 = (const float*)d_in[3];
    const float* b2 = (const float*)d_in[4];
    const float* w3 = (const float*)d_in[5];
    const float* b3 = (const float*)d_in[6];
    float* out = (float*)d_out;

    cudaFuncSetAttribute(cnn_main, cudaFuncAttributeMaxDynamicSharedMemorySize, SMEM_BYTES);
    cnn_main<<<NSEQ, 256, SMEM_BYTES>>>(x, w1, b1, w2, b2, w3, b3);
    final_pool<<<42, 256>>>(out);
}